// round 3
// baseline (speedup 1.0000x reference)
#include <cuda_runtime.h>
#include <math.h>

// Problem constants
#define NB 8
#define NQ 8
#define HID 4096
#define NH 32
#define NKVH 8
#define NG 4
#define DH 128
#define LKV 4096
#define NSPLIT 8
#define MR 64                    // B*Q rows
#define SPLIT_LEN (LKV / NSPLIT) // 512
#define CS 64                    // keys per chunk

// Scratch (device globals — no allocation allowed)
__device__ float g_q_raw[MR * HID];                    // GEMM1 output [m=(b,qq)][h*128+d]
__device__ float g_q[MR * HID];                        // roped, [bk=(b,kvh)][r=g*8+qq][d]
__device__ float g_attn[MR * HID];                     // merged attention out [(b,qq)][h*128+d]
__device__ float g_po[NB * NKVH * NSPLIT * 32 * DH];   // partial O (unnormalized)
__device__ float g_pm[NB * NKVH * NSPLIT * 32];        // partial running max
__device__ float g_pl[NB * NKVH * NSPLIT * 32];        // partial sum-exp
__device__ float g_cos[NB * 64];
__device__ float g_sin[NB * 64];

// ---------------------------------------------------------------------------
// Kernel 1: detect position_ids dtype (int32 vs int64), argmax over row 0
// (first occurrence, matching jnp.argmax), then per-batch cos/sin tables.
// JAX default config silently downcasts jnp.int64 -> int32, so int32 is the
// expected path; detection keeps us correct either way.
// ---------------------------------------------------------------------------
__global__ void rope_setup_kernel(const int* __restrict__ p32) {
    __shared__ int sv[256], si[256];
    __shared__ int s_is64, s_idx;
    int t = threadIdx.x;

    if (t == 0) {
        // True int64 positions (< 2^31) have zero high words at odd int32
        // slots. int32 arange has p32[1] == 1 != 0.
        int is64 = 1;
        for (int i = 1; i < 64; i += 2) {
            if (p32[i] != 0) { is64 = 0; break; }
        }
        s_is64 = is64;
    }
    __syncthreads();
    const int is64 = s_is64;
    const int stride = is64 ? 2 : 1;

    // argmax over row 0 (KV entries), first-occurrence tie-break
    int bv = -2147483647, bi = 0;
    for (int i = t; i < LKV; i += 256) {
        int v = p32[i * stride];   // low word == value (positions < 2^31)
        if (v > bv) { bv = v; bi = i; }
    }
    sv[t] = bv; si[t] = bi;
    __syncthreads();
    for (int off = 128; off > 0; off >>= 1) {
        if (t < off) {
            if (sv[t + off] > sv[t] || (sv[t + off] == sv[t] && si[t + off] < si[t])) {
                sv[t] = sv[t + off]; si[t] = si[t + off];
            }
        }
        __syncthreads();
    }
    if (t == 0) s_idx = si[0];
    __syncthreads();
    const int idx = s_idx;

    for (int i = t; i < NB * 64; i += 256) {
        int b = i >> 6, j = i & 63;
        long long pv;
        if (is64) pv = ((const long long*)p32)[b * LKV + idx];
        else      pv = (long long)p32[b * LKV + idx];
        double ang = (double)pv * pow(10000.0, -(double)j / 64.0);
        g_cos[i] = (float)cos(ang);
        g_sin[i] = (float)sin(ang);
    }
}

// ---------------------------------------------------------------------------
// GEMM: C[m][n] = sum_k A[m][k] * W[n][k],  m<64, n<4096, k<4096
// phase 0: A = hidden (Aext), C = g_q_raw
// phase 1: A = g_attn,        C = Cext (d_out)
// BM=64, BN=32, BK=32, 128 threads, 4x4 micro-tile, register prefetch.
// ---------------------------------------------------------------------------
__global__ __launch_bounds__(128) void gemm64_kernel(
    const float* __restrict__ Aext, const float* __restrict__ W,
    float* __restrict__ Cext, int phase)
{
    const float* A = phase ? g_attn : Aext;
    float* C = phase ? Cext : g_q_raw;

    __shared__ float As[64][33];  // [m][kk] stride-33: conflict-free
    __shared__ float Bs[32][33];  // [n][kk]

    int t = threadIdx.x;
    int nb = blockIdx.x * 32;
    int tx = t & 7, ty = t >> 3;
    int m0 = ty * 4, n0 = tx * 4;

    float acc[4][4] = {};
    float4 pa[4], pb[2];

    // prefetch k0 = 0
#pragma unroll
    for (int i = 0; i < 4; i++) {
        int idx = t + i * 128;
        pa[i] = *(const float4*)(A + (idx >> 3) * HID + (idx & 7) * 4);
    }
#pragma unroll
    for (int i = 0; i < 2; i++) {
        int idx = t + i * 128;
        pb[i] = *(const float4*)(W + (nb + (idx >> 3)) * HID + (idx & 7) * 4);
    }

    for (int k0 = 0; k0 < HID; k0 += 32) {
        __syncthreads();
#pragma unroll
        for (int i = 0; i < 4; i++) {
            int idx = t + i * 128;
            int m = idx >> 3, kq = idx & 7;
            As[m][kq * 4 + 0] = pa[i].x; As[m][kq * 4 + 1] = pa[i].y;
            As[m][kq * 4 + 2] = pa[i].z; As[m][kq * 4 + 3] = pa[i].w;
        }
#pragma unroll
        for (int i = 0; i < 2; i++) {
            int idx = t + i * 128;
            int n = idx >> 3, kq = idx & 7;
            Bs[n][kq * 4 + 0] = pb[i].x; Bs[n][kq * 4 + 1] = pb[i].y;
            Bs[n][kq * 4 + 2] = pb[i].z; Bs[n][kq * 4 + 3] = pb[i].w;
        }
        __syncthreads();

        int kn = k0 + 32;
        if (kn < HID) {
#pragma unroll
            for (int i = 0; i < 4; i++) {
                int idx = t + i * 128;
                pa[i] = *(const float4*)(A + (idx >> 3) * HID + kn + (idx & 7) * 4);
            }
#pragma unroll
            for (int i = 0; i < 2; i++) {
                int idx = t + i * 128;
                pb[i] = *(const float4*)(W + (nb + (idx >> 3)) * HID + kn + (idx & 7) * 4);
            }
        }

#pragma unroll
        for (int kk = 0; kk < 32; kk++) {
            float a0 = As[m0 + 0][kk], a1 = As[m0 + 1][kk];
            float a2 = As[m0 + 2][kk], a3 = As[m0 + 3][kk];
            float b0 = Bs[n0 + 0][kk], b1 = Bs[n0 + 1][kk];
            float b2 = Bs[n0 + 2][kk], b3 = Bs[n0 + 3][kk];
            acc[0][0] += a0 * b0; acc[0][1] += a0 * b1; acc[0][2] += a0 * b2; acc[0][3] += a0 * b3;
            acc[1][0] += a1 * b0; acc[1][1] += a1 * b1; acc[1][2] += a1 * b2; acc[1][3] += a1 * b3;
            acc[2][0] += a2 * b0; acc[2][1] += a2 * b1; acc[2][2] += a2 * b2; acc[2][3] += a2 * b3;
            acc[3][0] += a3 * b0; acc[3][1] += a3 * b1; acc[3][2] += a3 * b2; acc[3][3] += a3 * b3;
        }
    }

#pragma unroll
    for (int i = 0; i < 4; i++) {
        float4 v = make_float4(acc[i][0], acc[i][1], acc[i][2], acc[i][3]);
        *(float4*)(C + (m0 + i) * HID + nb + n0) = v;
    }
}

// ---------------------------------------------------------------------------
// Kernel 3: RoPE (single position per batch) + relayout for attention.
// ---------------------------------------------------------------------------
__global__ void rope_apply_kernel() {
    int i = blockIdx.x * 256 + threadIdx.x;   // 0 .. 262143
    int d = i & 127;
    int h = (i >> 7) & 31;
    int m = i >> 12;                          // (b,qq) row
    int b = m >> 3, qq = m & 7;
    int dj = d & 63;
    float c = g_cos[b * 64 + dj], s = g_sin[b * 64 + dj];
    float x = g_q_raw[m * HID + h * DH + d];
    float o = g_q_raw[m * HID + h * DH + ((d < 64) ? (d + 64) : (d - 64))];
    float val = (d < 64) ? (x * c - o * s) : (x * c + o * s);
    int kvh = h >> 2, g = h & 3;
    int r = g * NQ + qq;
    int bk = b * NKVH + kvh;
    g_q[(bk * 32 + r) * DH + d] = val;
}

// ---------------------------------------------------------------------------
// Kernel 4: split-KV flash attention.
// grid = (B*KVH)*NSPLIT = 512 blocks, 128 threads.
// Each block: 32 q-rows (G*Q), 512 keys in 8 chunks of 64. Online softmax,
// unnormalized partial output + (m, l) written per split.
// ---------------------------------------------------------------------------
__global__ __launch_bounds__(128) void attn_kernel(
    const float* __restrict__ Kc, const float* __restrict__ Vc)
{
    extern __shared__ float sm[];
    float* Qs = sm;            // [32][132]
    float* Ks = sm + 4224;     // [64][132]
    float* Vs = sm + 12672;    // [64][132]
    float* Sc = sm + 21120;    // [32][68]
    float* rm = sm + 23296;    // [32] running max
    float* rl = sm + 23328;    // [32] running sum
    float* rs = sm + 23360;    // [32] rescale factor

    int t = threadIdx.x;
    int blk = blockIdx.x;
    int sp = blk & 7;
    int bk = blk >> 3;
    const float* Kb = Kc + bk * LKV * DH;
    const float* Vb = Vc + bk * LKV * DH;

    // load Q tile (32x128) — float4, conflict-free
#pragma unroll
    for (int i = 0; i < 8; i++) {
        int idx = t + i * 128;
        int r = idx >> 5, dq = idx & 31;
        *(float4*)(Qs + r * 132 + dq * 4) =
            *(const float4*)(g_q + (bk * 32 + r) * DH + dq * 4);
    }
    if (t < 32) { rm[t] = -INFINITY; rl[t] = 0.0f; }

    // score micro-tile mapping: 4q x 4s (s strided by 16 for bank spread)
    int sx = t & 15, qy = t >> 4;
    int rq0 = qy * 4;
    // PV mapping: 2 q-rows x 16 d
    int rp = t >> 3, dp = t & 7;
    int r0 = rp * 2, d0 = dp * 16;
    float acc[2][16] = {};

    int s_base = sp * SPLIT_LEN;
    for (int ch = 0; ch < SPLIT_LEN / CS; ch++) {
        int sc0 = s_base + ch * CS;
        __syncthreads();  // prev PV done before K/V overwrite
#pragma unroll
        for (int i = 0; i < 16; i++) {
            int idx = t + i * 128;
            int s = idx >> 5, dq = idx & 31;
            *(float4*)(Ks + s * 132 + dq * 4) = *(const float4*)(Kb + (sc0 + s) * DH + dq * 4);
            *(float4*)(Vs + s * 132 + dq * 4) = *(const float4*)(Vb + (sc0 + s) * DH + dq * 4);
        }
        __syncthreads();

        // scores: 32x64 tile
        float sacc[4][4] = {};
#pragma unroll 4
        for (int d = 0; d < DH; d++) {
            float a0 = Qs[(rq0 + 0) * 132 + d], a1 = Qs[(rq0 + 1) * 132 + d];
            float a2 = Qs[(rq0 + 2) * 132 + d], a3 = Qs[(rq0 + 3) * 132 + d];
            float b0 = Ks[(sx + 0) * 132 + d], b1 = Ks[(sx + 16) * 132 + d];
            float b2 = Ks[(sx + 32) * 132 + d], b3 = Ks[(sx + 48) * 132 + d];
            sacc[0][0] += a0 * b0; sacc[0][1] += a0 * b1; sacc[0][2] += a0 * b2; sacc[0][3] += a0 * b3;
            sacc[1][0] += a1 * b0; sacc[1][1] += a1 * b1; sacc[1][2] += a1 * b2; sacc[1][3] += a1 * b3;
            sacc[2][0] += a2 * b0; sacc[2][1] += a2 * b1; sacc[2][2] += a2 * b2; sacc[2][3] += a2 * b3;
            sacc[3][0] += a3 * b0; sacc[3][1] += a3 * b1; sacc[3][2] += a3 * b2; sacc[3][3] += a3 * b3;
        }
        const float scl = 0.08838834764831845f;  // 1/sqrt(128)
#pragma unroll
        for (int i = 0; i < 4; i++) {
#pragma unroll
            for (int j = 0; j < 4; j++) {
                int sg = sc0 + sx + 16 * j;
                float v = sacc[i][j] * scl;
                if (sg > 4088 + ((rq0 + i) & 7)) v = -10000.0f;  // causal tail mask
                Sc[(rq0 + i) * 68 + sx + 16 * j] = v;
            }
        }
        __syncthreads();

        // online softmax update: warp w handles rows w*8 .. w*8+7
        {
            int lane = t & 31, w = t >> 5;
            for (int k = 0; k < 8; k++) {
                int rr = w * 8 + k;
                float v0 = Sc[rr * 68 + lane];
                float v1 = Sc[rr * 68 + 32 + lane];
                float mx = fmaxf(v0, v1);
#pragma unroll
                for (int off = 16; off > 0; off >>= 1)
                    mx = fmaxf(mx, __shfl_xor_sync(0xffffffffu, mx, off));
                float mprev = rm[rr];
                float mnew = fmaxf(mprev, mx);
                float p0 = __expf(v0 - mnew), p1 = __expf(v1 - mnew);
                Sc[rr * 68 + lane] = p0; Sc[rr * 68 + 32 + lane] = p1;
                float ls = p0 + p1;
#pragma unroll
                for (int off = 16; off > 0; off >>= 1)
                    ls += __shfl_xor_sync(0xffffffffu, ls, off);
                if (lane == 0) {
                    float f = __expf(mprev - mnew);  // exp(-inf)=0 on first chunk
                    rl[rr] = rl[rr] * f + ls;
                    rm[rr] = mnew;
                    rs[rr] = f;
                }
            }
        }
        __syncthreads();

        // rescale + PV
        float f0 = rs[r0], f1 = rs[r0 + 1];
#pragma unroll
        for (int j = 0; j < 16; j++) { acc[0][j] *= f0; acc[1][j] *= f1; }
#pragma unroll 2
        for (int s = 0; s < CS; s++) {
            float p0 = Sc[r0 * 68 + s], p1 = Sc[(r0 + 1) * 68 + s];
            const float* vrow = Vs + s * 132 + d0;
            float4 va = *(const float4*)(vrow);
            float4 vb = *(const float4*)(vrow + 4);
            float4 vc = *(const float4*)(vrow + 8);
            float4 vd = *(const float4*)(vrow + 12);
            acc[0][0]  += p0 * va.x; acc[0][1]  += p0 * va.y; acc[0][2]  += p0 * va.z; acc[0][3]  += p0 * va.w;
            acc[0][4]  += p0 * vb.x; acc[0][5]  += p0 * vb.y; acc[0][6]  += p0 * vb.z; acc[0][7]  += p0 * vb.w;
            acc[0][8]  += p0 * vc.x; acc[0][9]  += p0 * vc.y; acc[0][10] += p0 * vc.z; acc[0][11] += p0 * vc.w;
            acc[0][12] += p0 * vd.x; acc[0][13] += p0 * vd.y; acc[0][14] += p0 * vd.z; acc[0][15] += p0 * vd.w;
            acc[1][0]  += p1 * va.x; acc[1][1]  += p1 * va.y; acc[1][2]  += p1 * va.z; acc[1][3]  += p1 * va.w;
            acc[1][4]  += p1 * vb.x; acc[1][5]  += p1 * vb.y; acc[1][6]  += p1 * vb.z; acc[1][7]  += p1 * vb.w;
            acc[1][8]  += p1 * vc.x; acc[1][9]  += p1 * vc.y; acc[1][10] += p1 * vc.z; acc[1][11] += p1 * vc.w;
            acc[1][12] += p1 * vd.x; acc[1][13] += p1 * vd.y; acc[1][14] += p1 * vd.z; acc[1][15] += p1 * vd.w;
        }
    }
    __syncthreads();

    int pbase = (bk * NSPLIT + sp) * 32;
    if (t < 32) { g_pm[pbase + t] = rm[t]; g_pl[pbase + t] = rl[t]; }
#pragma unroll
    for (int i = 0; i < 2; i++) {
        float* dst = g_po + (pbase + r0 + i) * DH + d0;
        *(float4*)(dst + 0)  = make_float4(acc[i][0],  acc[i][1],  acc[i][2],  acc[i][3]);
        *(float4*)(dst + 4)  = make_float4(acc[i][4],  acc[i][5],  acc[i][6],  acc[i][7]);
        *(float4*)(dst + 8)  = make_float4(acc[i][8],  acc[i][9],  acc[i][10], acc[i][11]);
        *(float4*)(dst + 12) = make_float4(acc[i][12], acc[i][13], acc[i][14], acc[i][15]);
    }
}

// ---------------------------------------------------------------------------
// Kernel 5: merge split partials (log-sum-exp) + relayout to [(b,qq)][h*128+d]
// ---------------------------------------------------------------------------
__global__ void merge_kernel() {
    int i = blockIdx.x * 256 + threadIdx.x;   // 0 .. 262143
    int d = i & 127;
    int rg = i >> 7;                          // bk*32 + r
    int bk = rg >> 5, r = rg & 31;
    float mv[NSPLIT];
    float mmax = -INFINITY;
#pragma unroll
    for (int sp = 0; sp < NSPLIT; sp++) {
        mv[sp] = g_pm[(bk * NSPLIT + sp) * 32 + r];
        mmax = fmaxf(mmax, mv[sp]);
    }
    float num = 0.0f, den = 0.0f;
#pragma unroll
    for (int sp = 0; sp < NSPLIT; sp++) {
        float wgt = __expf(mv[sp] - mmax);
        num += wgt * g_po[((bk * NSPLIT + sp) * 32 + r) * DH + d];
        den += wgt * g_pl[(bk * NSPLIT + sp) * 32 + r];
    }
    float val = num / den;
    int b = bk >> 3, kvh = bk & 7, g = r >> 3, qq = r & 7;
    int h = kvh * NG + g;
    g_attn[(b * NQ + qq) * HID + h * DH + d] = val;
}

// ---------------------------------------------------------------------------
// kernel_launch: inputs per metadata order
//   0 hidden_states f32 [8,8,4096]   1 position_ids int (32 or 64) [8,4096]
//   2 key_cache f32 [8,8,4096,128]   3 value_cache f32 [8,8,4096,128]
//   4 attention_mask (unused — analytically reproduced)
//   5 q_w f32 [4096,4096]            6 o_w f32 [4096,4096]
// ---------------------------------------------------------------------------
extern "C" void kernel_launch(void* const* d_in, const int* in_sizes, int n_in,
                              void* d_out, int out_size) {
    (void)in_sizes; (void)n_in; (void)out_size;
    const float* hidden = (const float*)d_in[0];
    const int* pos = (const int*)d_in[1];
    const float* kc = (const float*)d_in[2];
    const float* vc = (const float*)d_in[3];
    const float* qw = (const float*)d_in[5];
    const float* ow = (const float*)d_in[6];
    float* out = (float*)d_out;

    cudaFuncSetAttribute(attn_kernel, cudaFuncAttributeMaxDynamicSharedMemorySize, 94000);

    rope_setup_kernel<<<1, 256>>>(pos);
    gemm64_kernel<<<128, 128>>>(hidden, qw, out, 0);
    rope_apply_kernel<<<1024, 256>>>();
    attn_kernel<<<512, 128, 93568>>>(kc, vc);
    merge_kernel<<<1024, 256>>>();
    gemm64_kernel<<<128, 128>>>(nullptr, ow, out, 1);
}

// round 4
// speedup vs baseline: 2.4050x; 2.4050x over previous
#include <cuda_runtime.h>
#include <cuda_bf16.h>
#include <math.h>
#include <stdint.h>

// Problem constants
#define NB 8
#define NQ 8
#define HID 4096
#define NH 32
#define NKVH 8
#define NG 4
#define DH 128
#define LKV 4096
#define NSPLIT 8
#define MR 64                    // B*Q rows
#define SPLIT_LEN (LKV / NSPLIT) // 512
#define CS 64                    // keys per chunk
#define KSPLIT 8                 // GEMM k-split

// Scratch (device globals — no allocation allowed)
__device__ float g_part[KSPLIT * MR * HID];             // GEMM split-K partials (8MB)
__device__ float g_q[MR * HID];                         // roped Q, [bk][r=g*8+qq][d]
__device__ float g_attn[MR * HID];                      // merged attn out [(b,qq)][h*128+d]
__device__ float g_po[NB * NKVH * NSPLIT * 32 * DH];    // partial O (unnormalized)
__device__ float g_pm[NB * NKVH * NSPLIT * 32];
__device__ float g_pl[NB * NKVH * NSPLIT * 32];
__device__ float g_cos[NB * 64];
__device__ float g_sin[NB * 64];

// ---------------------------------------------------------------------------
// bf16 hi/lo split helpers + m16n8k16 mma
// ---------------------------------------------------------------------------
__device__ __forceinline__ void split2(float x, float y, uint32_t& hi, uint32_t& lo) {
    __nv_bfloat16 hx = __float2bfloat16(x), hy = __float2bfloat16(y);
    float rx = x - __bfloat162float(hx);
    float ry = y - __bfloat162float(hy);
    __nv_bfloat16 lx = __float2bfloat16(rx), ly = __float2bfloat16(ry);
    __nv_bfloat162 h2 = __halves2bfloat162(hx, hy);   // hx in low half
    __nv_bfloat162 l2 = __halves2bfloat162(lx, ly);
    hi = *reinterpret_cast<uint32_t*>(&h2);
    lo = *reinterpret_cast<uint32_t*>(&l2);
}

__device__ __forceinline__ void mma_bf16(float c[4],
                                         uint32_t a0, uint32_t a1, uint32_t a2, uint32_t a3,
                                         uint32_t b0, uint32_t b1) {
    asm volatile(
        "mma.sync.aligned.m16n8k16.row.col.f32.bf16.bf16.f32 "
        "{%0,%1,%2,%3}, {%4,%5,%6,%7}, {%8,%9}, {%0,%1,%2,%3};\n"
        : "+f"(c[0]), "+f"(c[1]), "+f"(c[2]), "+f"(c[3])
        : "r"(a0), "r"(a1), "r"(a2), "r"(a3), "r"(b0), "r"(b1));
}

// ---------------------------------------------------------------------------
// Kernel 1: dtype-detect position_ids, argmax row 0, build cos/sin tables.
// ---------------------------------------------------------------------------
__global__ void rope_setup_kernel(const int* __restrict__ p32) {
    __shared__ int sv[256], si[256];
    __shared__ int s_is64, s_idx;
    int t = threadIdx.x;

    if (t == 0) {
        int is64 = 1;
        for (int i = 1; i < 64; i += 2)
            if (p32[i] != 0) { is64 = 0; break; }
        s_is64 = is64;
    }
    __syncthreads();
    const int is64 = s_is64;
    const int stride = is64 ? 2 : 1;

    int bv = -2147483647, bi = 0;
    for (int i = t; i < LKV; i += 256) {
        int v = p32[i * stride];
        if (v > bv) { bv = v; bi = i; }
    }
    sv[t] = bv; si[t] = bi;
    __syncthreads();
    for (int off = 128; off > 0; off >>= 1) {
        if (t < off) {
            if (sv[t + off] > sv[t] || (sv[t + off] == sv[t] && si[t + off] < si[t])) {
                sv[t] = sv[t + off]; si[t] = si[t + off];
            }
        }
        __syncthreads();
    }
    if (t == 0) s_idx = si[0];
    __syncthreads();
    const int idx = s_idx;

    for (int i = t; i < NB * 64; i += 256) {
        int b = i >> 6, j = i & 63;
        long long pv;
        if (is64) pv = ((const long long*)p32)[b * LKV + idx];
        else      pv = (long long)p32[b * LKV + idx];
        double ang = (double)pv * pow(10000.0, -(double)j / 64.0);
        g_cos[i] = (float)cos(ang);
        g_sin[i] = (float)sin(ang);
    }
}

// ---------------------------------------------------------------------------
// Tensor-core GEMM (bf16 3-pass split): part[ks][m][n] = sum_{k in slice}
// A[m][k] * W[n][k].  A: [64][4096] f32, W: [4096][4096] f32.
// Grid: (HID/64) x KSPLIT = 64 x 8.  256 threads = 8 warps.
// Warp w: m-tile (w&3)*16, n-half (w>>2)*32 (4 n-tiles of 8).
// ---------------------------------------------------------------------------
#define GSTR 20   // smem row stride in words (16 data + 4 pad -> conflict-free)
__global__ __launch_bounds__(256) void gemm_mma_kernel(
    const float* __restrict__ Aext, const float* __restrict__ W, int phase)
{
    const float* A = phase ? g_attn : Aext;

    __shared__ uint32_t Ah[64 * GSTR], Al[64 * GSTR];
    __shared__ uint32_t Wh[64 * GSTR], Wl[64 * GSTR];

    int t = threadIdx.x;
    int nb = blockIdx.x * 64;
    int ks = blockIdx.y;
    int k_begin = ks * (HID / KSPLIT);
    int w = t >> 5, lane = t & 31;
    int g = lane >> 2, tig = lane & 3;
    int wm = (w & 3) * 16;
    int wn = (w >> 2) * 32;

    float c[4][4] = {};

    for (int kc0 = k_begin; kc0 < k_begin + HID / KSPLIT; kc0 += 32) {
        __syncthreads();
        // load + convert A chunk (64x32) and W chunk (64x32)
#pragma unroll
        for (int i = 0; i < 2; i++) {
            int f4 = t + i * 256;           // 0..511
            int row = f4 >> 3, kq = f4 & 7; // kq*4 = k offset
            float4 va = *(const float4*)(A + row * HID + kc0 + kq * 4);
            uint32_t h0, l0, h1, l1;
            split2(va.x, va.y, h0, l0);
            split2(va.z, va.w, h1, l1);
            Ah[row * GSTR + kq * 2] = h0; Ah[row * GSTR + kq * 2 + 1] = h1;
            Al[row * GSTR + kq * 2] = l0; Al[row * GSTR + kq * 2 + 1] = l1;
            float4 vw = *(const float4*)(W + (size_t)(nb + row) * HID + kc0 + kq * 4);
            split2(vw.x, vw.y, h0, l0);
            split2(vw.z, vw.w, h1, l1);
            Wh[row * GSTR + kq * 2] = h0; Wh[row * GSTR + kq * 2 + 1] = h1;
            Wl[row * GSTR + kq * 2] = l0; Wl[row * GSTR + kq * 2 + 1] = l1;
        }
        __syncthreads();

#pragma unroll
        for (int kstep = 0; kstep < 2; kstep++) {
            int base = kstep * 8;
            uint32_t ah0 = Ah[(wm + g) * GSTR + base + tig];
            uint32_t ah1 = Ah[(wm + g + 8) * GSTR + base + tig];
            uint32_t ah2 = Ah[(wm + g) * GSTR + base + tig + 4];
            uint32_t ah3 = Ah[(wm + g + 8) * GSTR + base + tig + 4];
            uint32_t al0 = Al[(wm + g) * GSTR + base + tig];
            uint32_t al1 = Al[(wm + g + 8) * GSTR + base + tig];
            uint32_t al2 = Al[(wm + g) * GSTR + base + tig + 4];
            uint32_t al3 = Al[(wm + g + 8) * GSTR + base + tig + 4];
#pragma unroll
            for (int nt = 0; nt < 4; nt++) {
                int nrow = wn + nt * 8 + g;
                uint32_t bh0 = Wh[nrow * GSTR + base + tig];
                uint32_t bh1 = Wh[nrow * GSTR + base + tig + 4];
                uint32_t bl0 = Wl[nrow * GSTR + base + tig];
                uint32_t bl1 = Wl[nrow * GSTR + base + tig + 4];
                mma_bf16(c[nt], ah0, ah1, ah2, ah3, bh0, bh1);
                mma_bf16(c[nt], ah0, ah1, ah2, ah3, bl0, bl1);
                mma_bf16(c[nt], al0, al1, al2, al3, bh0, bh1);
            }
        }
    }

    float* P = g_part + (size_t)ks * MR * HID;
#pragma unroll
    for (int nt = 0; nt < 4; nt++) {
        int col = nb + wn + nt * 8 + tig * 2;
        int r0 = wm + g, r1 = wm + g + 8;
        P[r0 * HID + col] = c[nt][0]; P[r0 * HID + col + 1] = c[nt][1];
        P[r1 * HID + col] = c[nt][2]; P[r1 * HID + col + 1] = c[nt][3];
    }
}

// ---------------------------------------------------------------------------
// Reduce GEMM1 partials + RoPE + relayout into g_q.
// items: m(64) x h(32) x dj(64) = 131072
// ---------------------------------------------------------------------------
__global__ void rope_reduce_kernel() {
    int i = blockIdx.x * 256 + threadIdx.x;
    int dj = i & 63;
    int h = (i >> 6) & 31;
    int m = i >> 11;
    int c1 = h * DH + dj, c2 = c1 + 64;
    float x = 0.f, o = 0.f;
#pragma unroll
    for (int ks = 0; ks < KSPLIT; ks++) {
        x += g_part[ks * MR * HID + m * HID + c1];
        o += g_part[ks * MR * HID + m * HID + c2];
    }
    int b = m >> 3, qq = m & 7;
    float cc = g_cos[b * 64 + dj], ss = g_sin[b * 64 + dj];
    float v1 = x * cc - o * ss;
    float v2 = o * cc + x * ss;
    int kvh = h >> 2, gg = h & 3;
    int r = gg * NQ + qq;
    int bk = b * NKVH + kvh;
    g_q[(bk * 32 + r) * DH + dj] = v1;
    g_q[(bk * 32 + r) * DH + dj + 64] = v2;
}

// ---------------------------------------------------------------------------
// Reduce GEMM2 partials into d_out.
// ---------------------------------------------------------------------------
__global__ void reduce_out_kernel(float* __restrict__ out) {
    int i = blockIdx.x * 256 + threadIdx.x;   // 262144
    float s = 0.f;
#pragma unroll
    for (int ks = 0; ks < KSPLIT; ks++)
        s += g_part[ks * MR * HID + i];
    out[i] = s;
}

// ---------------------------------------------------------------------------
// Tensor-core split-KV flash attention (bf16 3-pass).
// grid = (B*KVH)*NSPLIT = 512 blocks, 128 threads = 4 warps.
// QK: warp = (m-half (w&1)*16) x (s-half (w>>1)*32); PV: (m-half) x (d-half 64).
// ---------------------------------------------------------------------------
#define KSTR 68   // K/Q smem stride words (64 + 4)
#define VSTR 36   // Vt / P stride words (32 + 4)
#define SSTR 66   // score stride floats

#define OFF_KH 0
#define OFF_KL (OFF_KH + 64 * KSTR)          // 4352
#define OFF_VH (OFF_KL + 64 * KSTR)          // 8704
#define OFF_VL (OFF_VH + 128 * VSTR)         // 13312
#define OFF_SC (OFF_VL + 128 * VSTR)         // 17920 (floats)
#define OFF_PH (OFF_SC + 32 * SSTR)          // 20032
#define OFF_PL (OFF_PH + 32 * VSTR)          // 21184
#define OFF_QH (OFF_PL + 32 * VSTR)          // 22336
#define OFF_QL (OFF_QH + 32 * KSTR)          // 24512
#define OFF_AUX (OFF_QL + 32 * KSTR)         // 26688
#define SMEM_WORDS (OFF_AUX + 96)            // 26784 words = 107136 B

__global__ __launch_bounds__(128) void attn_mma_kernel(
    const float* __restrict__ Kc, const float* __restrict__ Vc)
{
    extern __shared__ uint32_t sw[];
    uint32_t* Kh = sw + OFF_KH;
    uint32_t* Kl = sw + OFF_KL;
    uint32_t* Vh = sw + OFF_VH;
    uint32_t* Vl = sw + OFF_VL;
    float*    Sc = (float*)(sw + OFF_SC);
    uint32_t* Ph = sw + OFF_PH;
    uint32_t* Pl = sw + OFF_PL;
    uint32_t* Qh = sw + OFF_QH;
    uint32_t* Ql = sw + OFF_QL;
    float*    rm = (float*)(sw + OFF_AUX);
    float*    rl = rm + 32;
    float*    rs = rl + 32;

    int t = threadIdx.x;
    int w = t >> 5, lane = t & 31;
    int g = lane >> 2, tig = lane & 3;
    int sp = blockIdx.x & 7, bk = blockIdx.x >> 3;
    const float* Kb = Kc + (size_t)bk * LKV * DH;
    const float* Vb = Vc + (size_t)bk * LKV * DH;

    int qm = (w & 1) * 16;      // warp m-half (both QK and PV)
    int kn = (w >> 1) * 32;     // warp s-half for QK
    int dB = (w >> 1) * 64;     // warp d-half for PV

    // stage Q (32x128 f32) as packed bf16 hi/lo
#pragma unroll
    for (int i = 0; i < 8; i++) {
        int f4 = t + i * 128;                 // 0..1023
        int row = f4 >> 5, q4 = f4 & 31;
        float4 v = *(const float4*)(g_q + (size_t)(bk * 32 + row) * DH + q4 * 4);
        uint32_t h0, l0, h1, l1;
        split2(v.x, v.y, h0, l0);
        split2(v.z, v.w, h1, l1);
        Qh[row * KSTR + q4 * 2] = h0; Qh[row * KSTR + q4 * 2 + 1] = h1;
        Ql[row * KSTR + q4 * 2] = l0; Ql[row * KSTR + q4 * 2 + 1] = l1;
    }
    if (t < 32) { rm[t] = -INFINITY; rl[t] = 0.f; }
    __syncthreads();

    // hoist Q fragments to registers (constant across chunks)
    uint32_t qh[8][4], ql[8][4];
#pragma unroll
    for (int ksd = 0; ksd < 8; ksd++) {
        int base = ksd * 8;
        qh[ksd][0] = Qh[(qm + g) * KSTR + base + tig];
        qh[ksd][1] = Qh[(qm + g + 8) * KSTR + base + tig];
        qh[ksd][2] = Qh[(qm + g) * KSTR + base + tig + 4];
        qh[ksd][3] = Qh[(qm + g + 8) * KSTR + base + tig + 4];
        ql[ksd][0] = Ql[(qm + g) * KSTR + base + tig];
        ql[ksd][1] = Ql[(qm + g + 8) * KSTR + base + tig];
        ql[ksd][2] = Ql[(qm + g) * KSTR + base + tig + 4];
        ql[ksd][3] = Ql[(qm + g + 8) * KSTR + base + tig + 4];
    }

    float o[8][4] = {};   // PV accum: 8 d-tiles x {c0,c1 (row g), c2,c3 (row g+8)}
    const float scl = 0.08838834764831845f;

    for (int ch = 0; ch < SPLIT_LEN / CS; ch++) {
        int sc0 = sp * SPLIT_LEN + ch * CS;
        __syncthreads();  // previous PV must be done before K/V overwrite

        // load K chunk (64 x 128) -> Kh/Kl packed along d
#pragma unroll
        for (int i = 0; i < 16; i++) {
            int f4 = t + i * 128;             // 0..2047
            int row = f4 >> 5, q4 = f4 & 31;
            float4 v = *(const float4*)(Kb + (size_t)(sc0 + row) * DH + q4 * 4);
            uint32_t h0, l0, h1, l1;
            split2(v.x, v.y, h0, l0);
            split2(v.z, v.w, h1, l1);
            Kh[row * KSTR + q4 * 2] = h0; Kh[row * KSTR + q4 * 2 + 1] = h1;
            Kl[row * KSTR + q4 * 2] = l0; Kl[row * KSTR + q4 * 2 + 1] = l1;
        }
        // load V chunk transposed: Vt[d][s-pair] packed along s
#pragma unroll
        for (int i = 0; i < 8; i++) {
            int task = t + i * 128;           // 0..1023
            int spair = task >> 5, dq = task & 31;
            float4 va = *(const float4*)(Vb + (size_t)(sc0 + spair * 2) * DH + dq * 4);
            float4 vb = *(const float4*)(Vb + (size_t)(sc0 + spair * 2 + 1) * DH + dq * 4);
            const float* pa = &va.x;
            const float* pb = &vb.x;
#pragma unroll
            for (int j = 0; j < 4; j++) {
                int d = dq * 4 + j;
                uint32_t h, l;
                split2(pa[j], pb[j], h, l);
                Vh[d * VSTR + spair] = h;
                Vl[d * VSTR + spair] = l;
            }
        }
        __syncthreads();

        // QK^T: S[32][64]
        float s4[4][4] = {};
#pragma unroll
        for (int ksd = 0; ksd < 8; ksd++) {
            int base = ksd * 8;
#pragma unroll
            for (int nt = 0; nt < 4; nt++) {
                int srow = kn + nt * 8 + g;
                uint32_t bh0 = Kh[srow * KSTR + base + tig];
                uint32_t bh1 = Kh[srow * KSTR + base + tig + 4];
                uint32_t bl0 = Kl[srow * KSTR + base + tig];
                uint32_t bl1 = Kl[srow * KSTR + base + tig + 4];
                mma_bf16(s4[nt], qh[ksd][0], qh[ksd][1], qh[ksd][2], qh[ksd][3], bh0, bh1);
                mma_bf16(s4[nt], qh[ksd][0], qh[ksd][1], qh[ksd][2], qh[ksd][3], bl0, bl1);
                mma_bf16(s4[nt], ql[ksd][0], ql[ksd][1], ql[ksd][2], ql[ksd][3], bh0, bh1);
            }
        }
        // scale + causal mask + store scores
#pragma unroll
        for (int nt = 0; nt < 4; nt++) {
            int col = kn + nt * 8 + tig * 2;
            int r0 = qm + g, r1 = qm + g + 8;
            int sg0 = sc0 + col, sg1 = sg0 + 1;
            float v00 = s4[nt][0] * scl, v01 = s4[nt][1] * scl;
            float v10 = s4[nt][2] * scl, v11 = s4[nt][3] * scl;
            if (sg0 > 4088 + (r0 & 7)) v00 = -10000.f;
            if (sg1 > 4088 + (r0 & 7)) v01 = -10000.f;
            if (sg0 > 4088 + (r1 & 7)) v10 = -10000.f;
            if (sg1 > 4088 + (r1 & 7)) v11 = -10000.f;
            Sc[r0 * SSTR + col] = v00; Sc[r0 * SSTR + col + 1] = v01;
            Sc[r1 * SSTR + col] = v10; Sc[r1 * SSTR + col + 1] = v11;
        }
        __syncthreads();

        // online softmax: warp w handles rows w*8..w*8+7; lane -> s = 2*lane, 2*lane+1
#pragma unroll
        for (int k2 = 0; k2 < 8; k2++) {
            int rr = w * 8 + k2;
            float v0 = Sc[rr * SSTR + 2 * lane];
            float v1 = Sc[rr * SSTR + 2 * lane + 1];
            float mx = fmaxf(v0, v1);
#pragma unroll
            for (int off = 16; off > 0; off >>= 1)
                mx = fmaxf(mx, __shfl_xor_sync(0xffffffffu, mx, off));
            float mprev = rm[rr];
            float mnew = fmaxf(mprev, mx);
            float p0 = __expf(v0 - mnew), p1 = __expf(v1 - mnew);
            uint32_t hh, ll;
            split2(p0, p1, hh, ll);
            Ph[rr * VSTR + lane] = hh;
            Pl[rr * VSTR + lane] = ll;
            float ls = p0 + p1;
#pragma unroll
            for (int off = 16; off > 0; off >>= 1)
                ls += __shfl_xor_sync(0xffffffffu, ls, off);
            if (lane == 0) {
                float f = __expf(mprev - mnew);
                rl[rr] = rl[rr] * f + ls;
                rm[rr] = mnew;
                rs[rr] = f;
            }
        }
        __syncthreads();

        // rescale accumulators
        float f0 = rs[qm + g], f1 = rs[qm + g + 8];
#pragma unroll
        for (int nt = 0; nt < 8; nt++) {
            o[nt][0] *= f0; o[nt][1] *= f0;
            o[nt][2] *= f1; o[nt][3] *= f1;
        }
        // PV: O[32][128] += P[32][64] @ V[64][128]
#pragma unroll
        for (int ksp = 0; ksp < 4; ksp++) {
            int base = ksp * 8;
            uint32_t ah0 = Ph[(qm + g) * VSTR + base + tig];
            uint32_t ah1 = Ph[(qm + g + 8) * VSTR + base + tig];
            uint32_t ah2 = Ph[(qm + g) * VSTR + base + tig + 4];
            uint32_t ah3 = Ph[(qm + g + 8) * VSTR + base + tig + 4];
            uint32_t al0 = Pl[(qm + g) * VSTR + base + tig];
            uint32_t al1 = Pl[(qm + g + 8) * VSTR + base + tig];
            uint32_t al2 = Pl[(qm + g) * VSTR + base + tig + 4];
            uint32_t al3 = Pl[(qm + g + 8) * VSTR + base + tig + 4];
#pragma unroll
            for (int nt = 0; nt < 8; nt++) {
                int drow = dB + nt * 8 + g;
                uint32_t bh0 = Vh[drow * VSTR + base + tig];
                uint32_t bh1 = Vh[drow * VSTR + base + tig + 4];
                uint32_t bl0 = Vl[drow * VSTR + base + tig];
                uint32_t bl1 = Vl[drow * VSTR + base + tig + 4];
                mma_bf16(o[nt], ah0, ah1, ah2, ah3, bh0, bh1);
                mma_bf16(o[nt], ah0, ah1, ah2, ah3, bl0, bl1);
                mma_bf16(o[nt], al0, al1, al2, al3, bh0, bh1);
            }
        }
    }
    __syncthreads();

    int pbase = (bk * NSPLIT + sp) * 32;
    if (t < 32) { g_pm[pbase + t] = rm[t]; g_pl[pbase + t] = rl[t]; }
#pragma unroll
    for (int nt = 0; nt < 8; nt++) {
        int col = dB + nt * 8 + tig * 2;
        int r0 = qm + g, r1 = qm + g + 8;
        g_po[(size_t)(pbase + r0) * DH + col] = o[nt][0];
        g_po[(size_t)(pbase + r0) * DH + col + 1] = o[nt][1];
        g_po[(size_t)(pbase + r1) * DH + col] = o[nt][2];
        g_po[(size_t)(pbase + r1) * DH + col + 1] = o[nt][3];
    }
}

// ---------------------------------------------------------------------------
// Merge split partials (log-sum-exp) + relayout to [(b,qq)][h*128+d]
// ---------------------------------------------------------------------------
__global__ void merge_kernel() {
    int i = blockIdx.x * 256 + threadIdx.x;   // 0 .. 262143
    int d = i & 127;
    int rg = i >> 7;
    int bk = rg >> 5, r = rg & 31;
    float mv[NSPLIT];
    float mmax = -INFINITY;
#pragma unroll
    for (int sp = 0; sp < NSPLIT; sp++) {
        mv[sp] = g_pm[(bk * NSPLIT + sp) * 32 + r];
        mmax = fmaxf(mmax, mv[sp]);
    }
    float num = 0.f, den = 0.f;
#pragma unroll
    for (int sp = 0; sp < NSPLIT; sp++) {
        float wgt = __expf(mv[sp] - mmax);
        num += wgt * g_po[(size_t)((bk * NSPLIT + sp) * 32 + r) * DH + d];
        den += wgt * g_pl[(bk * NSPLIT + sp) * 32 + r];
    }
    float val = num / den;
    int b = bk >> 3, kvh = bk & 7, gg = r >> 3, qq = r & 7;
    int h = kvh * NG + gg;
    g_attn[(b * NQ + qq) * HID + h * DH + d] = val;
}

// ---------------------------------------------------------------------------
// kernel_launch
// ---------------------------------------------------------------------------
extern "C" void kernel_launch(void* const* d_in, const int* in_sizes, int n_in,
                              void* d_out, int out_size) {
    (void)in_sizes; (void)n_in; (void)out_size;
    const float* hidden = (const float*)d_in[0];
    const int* pos = (const int*)d_in[1];
    const float* kc = (const float*)d_in[2];
    const float* vc = (const float*)d_in[3];
    const float* qw = (const float*)d_in[5];
    const float* ow = (const float*)d_in[6];
    float* out = (float*)d_out;

    static int attr_done = 0;
    if (!attr_done) {
        cudaFuncSetAttribute(attn_mma_kernel,
                             cudaFuncAttributeMaxDynamicSharedMemorySize,
                             SMEM_WORDS * 4);
        attr_done = 1;
    }

    rope_setup_kernel<<<1, 256>>>(pos);
    gemm_mma_kernel<<<dim3(HID / 64, KSPLIT), 256>>>(hidden, qw, 0);
    rope_reduce_kernel<<<512, 256>>>();
    attn_mma_kernel<<<512, 128, SMEM_WORDS * 4>>>(kc, vc);
    merge_kernel<<<1024, 256>>>();
    gemm_mma_kernel<<<dim3(HID / 64, KSPLIT), 256>>>(nullptr, ow, 1);
    reduce_out_kernel<<<1024, 256>>>(out);
}

// round 5
// speedup vs baseline: 3.1418x; 1.3064x over previous
#include <cuda_runtime.h>
#include <cuda_bf16.h>
#include <math.h>
#include <stdint.h>

// Problem constants
#define NB 8
#define NQ 8
#define HID 4096
#define NH 32
#define NKVH 8
#define NG 4
#define DH 128
#define LKV 4096
#define NSPLIT 16
#define MR 64                    // B*Q rows
#define SPLIT_LEN (LKV / NSPLIT) // 256
#define CS 32                    // keys per chunk
#define NCH (SPLIT_LEN / CS)     // 8
#define KSPLIT 8                 // GEMM k-split

// Scratch (device globals — no allocation allowed)
__device__ float g_part[KSPLIT * MR * HID];             // GEMM split-K partials (8MB)
__device__ float g_q[MR * HID];                         // roped+scaled Q, [bk][r][d]
__device__ float g_attn[MR * HID];                      // merged attn out [(b,qq)][h*128+d]
__device__ float g_po[NB * NKVH * NSPLIT * 32 * DH];    // partial O (unnormalized)
__device__ float g_pm[NB * NKVH * NSPLIT * 32];
__device__ float g_pl[NB * NKVH * NSPLIT * 32];
__device__ float g_cos[NB * 64];
__device__ float g_sin[NB * 64];

// ---------------------------------------------------------------------------
// bf16 hi/lo split helpers + m16n8k16 mma
// ---------------------------------------------------------------------------
__device__ __forceinline__ void split2(float x, float y, uint32_t& hi, uint32_t& lo) {
    __nv_bfloat16 hx = __float2bfloat16(x), hy = __float2bfloat16(y);
    float rx = x - __bfloat162float(hx);
    float ry = y - __bfloat162float(hy);
    __nv_bfloat16 lx = __float2bfloat16(rx), ly = __float2bfloat16(ry);
    __nv_bfloat162 h2 = __halves2bfloat162(hx, hy);
    __nv_bfloat162 l2 = __halves2bfloat162(lx, ly);
    hi = *reinterpret_cast<uint32_t*>(&h2);
    lo = *reinterpret_cast<uint32_t*>(&l2);
}

__device__ __forceinline__ void mma_bf16(float c[4],
                                         uint32_t a0, uint32_t a1, uint32_t a2, uint32_t a3,
                                         uint32_t b0, uint32_t b1) {
    asm volatile(
        "mma.sync.aligned.m16n8k16.row.col.f32.bf16.bf16.f32 "
        "{%0,%1,%2,%3}, {%4,%5,%6,%7}, {%8,%9}, {%0,%1,%2,%3};\n"
        : "+f"(c[0]), "+f"(c[1]), "+f"(c[2]), "+f"(c[3])
        : "r"(a0), "r"(a1), "r"(a2), "r"(a3), "r"(b0), "r"(b1));
}

// ---------------------------------------------------------------------------
// Kernel 1: dtype-detect position_ids, argmax row 0, cos/sin tables.
// ---------------------------------------------------------------------------
__global__ void rope_setup_kernel(const int* __restrict__ p32) {
    __shared__ int sv[256], si[256];
    __shared__ int s_is64, s_idx;
    int t = threadIdx.x;

    if (t == 0) {
        int is64 = 1;
        for (int i = 1; i < 64; i += 2)
            if (p32[i] != 0) { is64 = 0; break; }
        s_is64 = is64;
    }
    __syncthreads();
    const int is64 = s_is64;
    const int stride = is64 ? 2 : 1;

    int bv = -2147483647, bi = 0;
    for (int i = t; i < LKV; i += 256) {
        int v = p32[i * stride];
        if (v > bv) { bv = v; bi = i; }
    }
    sv[t] = bv; si[t] = bi;
    __syncthreads();
    for (int off = 128; off > 0; off >>= 1) {
        if (t < off) {
            if (sv[t + off] > sv[t] || (sv[t + off] == sv[t] && si[t + off] < si[t])) {
                sv[t] = sv[t + off]; si[t] = si[t + off];
            }
        }
        __syncthreads();
    }
    if (t == 0) s_idx = si[0];
    __syncthreads();
    const int idx = s_idx;

    for (int i = t; i < NB * 64; i += 256) {
        int b = i >> 6, j = i & 63;
        long long pv;
        if (is64) pv = ((const long long*)p32)[b * LKV + idx];
        else      pv = (long long)p32[b * LKV + idx];
        double ang = (double)pv * pow(10000.0, -(double)j / 64.0);
        g_cos[i] = (float)cos(ang);
        g_sin[i] = (float)sin(ang);
    }
}

// ---------------------------------------------------------------------------
// Tensor-core GEMM (bf16 3-pass, register-prefetch pipeline).
// part[ks][m][n] = sum_{k slice} A[m][k] * W[n][k]
// Grid: 64 x KSPLIT, 256 threads (8 warps). Warp: m-tile (w&3)*16, n-half (w>>2)*32.
// ---------------------------------------------------------------------------
#define GSTR 20
__global__ __launch_bounds__(256) void gemm_mma_kernel(
    const float* __restrict__ Aext, const float* __restrict__ W, int phase)
{
    const float* A = phase ? g_attn : Aext;

    __shared__ uint32_t Ah[64 * GSTR], Al[64 * GSTR];
    __shared__ uint32_t Wh[64 * GSTR], Wl[64 * GSTR];

    int t = threadIdx.x;
    int nb = blockIdx.x * 64;
    int ks = blockIdx.y;
    int k_begin = ks * (HID / KSPLIT);
    int k_end = k_begin + HID / KSPLIT;
    int w = t >> 5, lane = t & 31;
    int g = lane >> 2, tig = lane & 3;
    int wm = (w & 3) * 16;
    int wn = (w >> 2) * 32;

    float c[4][4] = {};
    float4 va[2], vw[2];

    // prologue prefetch
#pragma unroll
    for (int i = 0; i < 2; i++) {
        int f4 = t + i * 256;
        int row = f4 >> 3, kq = f4 & 7;
        va[i] = *(const float4*)(A + (size_t)row * HID + k_begin + kq * 4);
        vw[i] = *(const float4*)(W + (size_t)(nb + row) * HID + k_begin + kq * 4);
    }

    for (int kc0 = k_begin; kc0 < k_end; kc0 += 32) {
        __syncthreads();
#pragma unroll
        for (int i = 0; i < 2; i++) {
            int f4 = t + i * 256;
            int row = f4 >> 3, kq = f4 & 7;
            uint32_t h0, l0, h1, l1;
            split2(va[i].x, va[i].y, h0, l0);
            split2(va[i].z, va[i].w, h1, l1);
            *(uint2*)&Ah[row * GSTR + kq * 2] = make_uint2(h0, h1);
            *(uint2*)&Al[row * GSTR + kq * 2] = make_uint2(l0, l1);
            split2(vw[i].x, vw[i].y, h0, l0);
            split2(vw[i].z, vw[i].w, h1, l1);
            *(uint2*)&Wh[row * GSTR + kq * 2] = make_uint2(h0, h1);
            *(uint2*)&Wl[row * GSTR + kq * 2] = make_uint2(l0, l1);
        }
        __syncthreads();

        int kn2 = kc0 + 32;
        if (kn2 < k_end) {
#pragma unroll
            for (int i = 0; i < 2; i++) {
                int f4 = t + i * 256;
                int row = f4 >> 3, kq = f4 & 7;
                va[i] = *(const float4*)(A + (size_t)row * HID + kn2 + kq * 4);
                vw[i] = *(const float4*)(W + (size_t)(nb + row) * HID + kn2 + kq * 4);
            }
        }

#pragma unroll
        for (int kstep = 0; kstep < 2; kstep++) {
            int base = kstep * 8;
            uint32_t ah0 = Ah[(wm + g) * GSTR + base + tig];
            uint32_t ah1 = Ah[(wm + g + 8) * GSTR + base + tig];
            uint32_t ah2 = Ah[(wm + g) * GSTR + base + tig + 4];
            uint32_t ah3 = Ah[(wm + g + 8) * GSTR + base + tig + 4];
            uint32_t al0 = Al[(wm + g) * GSTR + base + tig];
            uint32_t al1 = Al[(wm + g + 8) * GSTR + base + tig];
            uint32_t al2 = Al[(wm + g) * GSTR + base + tig + 4];
            uint32_t al3 = Al[(wm + g + 8) * GSTR + base + tig + 4];
#pragma unroll
            for (int nt = 0; nt < 4; nt++) {
                int nrow = wn + nt * 8 + g;
                uint32_t bh0 = Wh[nrow * GSTR + base + tig];
                uint32_t bh1 = Wh[nrow * GSTR + base + tig + 4];
                uint32_t bl0 = Wl[nrow * GSTR + base + tig];
                uint32_t bl1 = Wl[nrow * GSTR + base + tig + 4];
                mma_bf16(c[nt], ah0, ah1, ah2, ah3, bh0, bh1);
                mma_bf16(c[nt], ah0, ah1, ah2, ah3, bl0, bl1);
                mma_bf16(c[nt], al0, al1, al2, al3, bh0, bh1);
            }
        }
    }

    float* P = g_part + (size_t)ks * MR * HID;
#pragma unroll
    for (int nt = 0; nt < 4; nt++) {
        int col = nb + wn + nt * 8 + tig * 2;
        int r0 = wm + g, r1 = wm + g + 8;
        P[r0 * HID + col] = c[nt][0]; P[r0 * HID + col + 1] = c[nt][1];
        P[r1 * HID + col] = c[nt][2]; P[r1 * HID + col + 1] = c[nt][3];
    }
}

// ---------------------------------------------------------------------------
// Reduce GEMM1 partials + RoPE + scale by 1/sqrt(D) + relayout into g_q.
// ---------------------------------------------------------------------------
__global__ void rope_reduce_kernel() {
    const float scl = 0.08838834764831845f;  // 1/sqrt(128)
    int i = blockIdx.x * 256 + threadIdx.x;
    int dj = i & 63;
    int h = (i >> 6) & 31;
    int m = i >> 11;
    int c1 = h * DH + dj, c2 = c1 + 64;
    float x = 0.f, o = 0.f;
#pragma unroll
    for (int ks = 0; ks < KSPLIT; ks++) {
        x += g_part[ks * MR * HID + m * HID + c1];
        o += g_part[ks * MR * HID + m * HID + c2];
    }
    int b = m >> 3, qq = m & 7;
    float cc = g_cos[b * 64 + dj], ss = g_sin[b * 64 + dj];
    float v1 = (x * cc - o * ss) * scl;
    float v2 = (o * cc + x * ss) * scl;
    int kvh = h >> 2, gg = h & 3;
    int r = gg * NQ + qq;
    int bk = b * NKVH + kvh;
    g_q[(bk * 32 + r) * DH + dj] = v1;
    g_q[(bk * 32 + r) * DH + dj + 64] = v2;
}

// ---------------------------------------------------------------------------
// Reduce GEMM2 partials into d_out.
// ---------------------------------------------------------------------------
__global__ void reduce_out_kernel(float* __restrict__ out) {
    int i = blockIdx.x * 256 + threadIdx.x;
    float s = 0.f;
#pragma unroll
    for (int ks = 0; ks < KSPLIT; ks++)
        s += g_part[ks * MR * HID + i];
    out[i] = s;
}

// ---------------------------------------------------------------------------
// Split-KV flash attention: 1024 blocks (64 bk x 16 splits), 256 thr (8 warps),
// CS=32 chunks, register-prefetch pipeline, conflict-free smem layouts.
// Warp roles: QK (m-half (w&1)*16) x (s-eighth (w>>1)*8);
//             PV (m-half) x (d-quarter (w>>1)*32).
// ---------------------------------------------------------------------------
#define QSTR 68    // Q/K row stride (64 words + 4 pad)
#define VSTR 17    // Vt row stride (16 spairs + 1)
#define SSTR 33    // score row stride
#define PSTR 17    // P row stride

#define OFF_QH 0
#define OFF_QL (OFF_QH + 32 * QSTR)          // 2176
#define OFF_KH (OFF_QL + 32 * QSTR)          // 4352
#define OFF_KL (OFF_KH + 32 * QSTR)          // 6528
#define OFF_VH (OFF_KL + 32 * QSTR)          // 8704
#define OFF_VL (OFF_VH + 128 * VSTR)         // 10880
#define OFF_SC (OFF_VL + 128 * VSTR)         // 13056
#define OFF_PH (OFF_SC + 32 * SSTR)          // 14112
#define OFF_PL (OFF_PH + 32 * PSTR)          // 14656
#define OFF_AUX (OFF_PL + 32 * PSTR)         // 15200
#define SMEM_WORDS (OFF_AUX + 96)            // 15296 words = 61184 B

__global__ __launch_bounds__(256, 2) void attn_mma_kernel(
    const float* __restrict__ Kc, const float* __restrict__ Vc)
{
    extern __shared__ uint32_t sw[];
    uint32_t* Qh = sw + OFF_QH;
    uint32_t* Ql = sw + OFF_QL;
    uint32_t* Kh = sw + OFF_KH;
    uint32_t* Kl = sw + OFF_KL;
    uint32_t* Vh = sw + OFF_VH;
    uint32_t* Vl = sw + OFF_VL;
    float*    Sc = (float*)(sw + OFF_SC);
    uint32_t* Ph = sw + OFF_PH;
    uint32_t* Pl = sw + OFF_PL;
    float*    rm = (float*)(sw + OFF_AUX);
    float*    rl = rm + 32;
    float*    rs = rl + 32;

    int t = threadIdx.x;
    int w = t >> 5, lane = t & 31;
    int g = lane >> 2, tig = lane & 3;
    int sp = blockIdx.x & (NSPLIT - 1), bk = blockIdx.x >> 4;
    const float* Kb = Kc + (size_t)bk * LKV * DH;
    const float* Vb = Vc + (size_t)bk * LKV * DH;

    int qm = (w & 1) * 16;      // m-half
    int kn = (w >> 1) * 8;      // QK col base (8 cols per warp)
    int dB = (w >> 1) * 32;     // PV d base

    // stage Q (pre-scaled by 1/sqrt(D) in rope_reduce)
#pragma unroll
    for (int i = 0; i < 4; i++) {
        int f4 = t + i * 256;
        int row = f4 >> 5, q4 = f4 & 31;
        float4 v = *(const float4*)(g_q + (size_t)(bk * 32 + row) * DH + q4 * 4);
        uint32_t h0, l0, h1, l1;
        split2(v.x, v.y, h0, l0);
        split2(v.z, v.w, h1, l1);
        *(uint2*)&Qh[row * QSTR + q4 * 2] = make_uint2(h0, h1);
        *(uint2*)&Ql[row * QSTR + q4 * 2] = make_uint2(l0, l1);
    }
    if (t < 32) { rm[t] = -INFINITY; rl[t] = 0.f; }

    float o[4][4] = {};
    float4 kreg[4];
    float  vreg[16];

    int s_base = sp * SPLIT_LEN;

    // prologue: prefetch chunk 0
    {
#pragma unroll
        for (int i = 0; i < 4; i++) {
            int f4 = t + i * 256;
            int row = f4 >> 5, q4 = f4 & 31;
            kreg[i] = *(const float4*)(Kb + (size_t)(s_base + row) * DH + q4 * 4);
        }
#pragma unroll
        for (int i = 0; i < 2; i++) {
            int spair = w + 8 * i;
#pragma unroll
            for (int j = 0; j < 4; j++) {
                int d = lane + 32 * j;
                vreg[i * 8 + j * 2]     = Vb[(size_t)(s_base + 2 * spair) * DH + d];
                vreg[i * 8 + j * 2 + 1] = Vb[(size_t)(s_base + 2 * spair + 1) * DH + d];
            }
        }
    }

    for (int ch = 0; ch < NCH; ch++) {
        int sc0 = s_base + ch * CS;
        __syncthreads();   // prev PV done; smem K/V free (covers Q staging on first iter)

        // STS current chunk from registers (conflict-free)
#pragma unroll
        for (int i = 0; i < 4; i++) {
            int f4 = t + i * 256;
            int row = f4 >> 5, q4 = f4 & 31;
            uint32_t h0, l0, h1, l1;
            split2(kreg[i].x, kreg[i].y, h0, l0);
            split2(kreg[i].z, kreg[i].w, h1, l1);
            *(uint2*)&Kh[row * QSTR + q4 * 2] = make_uint2(h0, h1);
            *(uint2*)&Kl[row * QSTR + q4 * 2] = make_uint2(l0, l1);
        }
#pragma unroll
        for (int i = 0; i < 2; i++) {
            int spair = w + 8 * i;
#pragma unroll
            for (int j = 0; j < 4; j++) {
                int d = lane + 32 * j;
                uint32_t h, l;
                split2(vreg[i * 8 + j * 2], vreg[i * 8 + j * 2 + 1], h, l);
                Vh[d * VSTR + spair] = h;
                Vl[d * VSTR + spair] = l;
            }
        }
        __syncthreads();

        // prefetch next chunk (consumed next iteration -> latency hidden)
        if (ch + 1 < NCH) {
            int sn = sc0 + CS;
#pragma unroll
            for (int i = 0; i < 4; i++) {
                int f4 = t + i * 256;
                int row = f4 >> 5, q4 = f4 & 31;
                kreg[i] = *(const float4*)(Kb + (size_t)(sn + row) * DH + q4 * 4);
            }
#pragma unroll
            for (int i = 0; i < 2; i++) {
                int spair = w + 8 * i;
#pragma unroll
                for (int j = 0; j < 4; j++) {
                    int d = lane + 32 * j;
                    vreg[i * 8 + j * 2]     = Vb[(size_t)(sn + 2 * spair) * DH + d];
                    vreg[i * 8 + j * 2 + 1] = Vb[(size_t)(sn + 2 * spair + 1) * DH + d];
                }
            }
        }

        // QK^T: warp computes 16 q-rows x 8 s-cols
        float s4[4] = {0.f, 0.f, 0.f, 0.f};
#pragma unroll
        for (int ksd = 0; ksd < 8; ksd++) {
            int base = ksd * 8;
            int srow = kn + g;
            uint32_t ah0 = Qh[(qm + g) * QSTR + base + tig];
            uint32_t ah1 = Qh[(qm + g + 8) * QSTR + base + tig];
            uint32_t ah2 = Qh[(qm + g) * QSTR + base + tig + 4];
            uint32_t ah3 = Qh[(qm + g + 8) * QSTR + base + tig + 4];
            uint32_t al0 = Ql[(qm + g) * QSTR + base + tig];
            uint32_t al1 = Ql[(qm + g + 8) * QSTR + base + tig];
            uint32_t al2 = Ql[(qm + g) * QSTR + base + tig + 4];
            uint32_t al3 = Ql[(qm + g + 8) * QSTR + base + tig + 4];
            uint32_t bh0 = Kh[srow * QSTR + base + tig];
            uint32_t bh1 = Kh[srow * QSTR + base + tig + 4];
            uint32_t bl0 = Kl[srow * QSTR + base + tig];
            uint32_t bl1 = Kl[srow * QSTR + base + tig + 4];
            mma_bf16(s4, ah0, ah1, ah2, ah3, bh0, bh1);
            mma_bf16(s4, ah0, ah1, ah2, ah3, bl0, bl1);
            mma_bf16(s4, al0, al1, al2, al3, bh0, bh1);
        }
        {
            int col = kn + tig * 2;
            int r0 = qm + g, r1 = qm + g + 8;
            int sg0 = sc0 + col, sg1 = sg0 + 1;
            float v00 = s4[0], v01 = s4[1], v10 = s4[2], v11 = s4[3];
            if (sg0 > 4088 + (r0 & 7)) v00 = -10000.f;
            if (sg1 > 4088 + (r0 & 7)) v01 = -10000.f;
            if (sg0 > 4088 + (r1 & 7)) v10 = -10000.f;
            if (sg1 > 4088 + (r1 & 7)) v11 = -10000.f;
            Sc[r0 * SSTR + col] = v00; Sc[r0 * SSTR + col + 1] = v01;
            Sc[r1 * SSTR + col] = v10; Sc[r1 * SSTR + col + 1] = v11;
        }
        __syncthreads();

        // online softmax: warp w owns rows w*4 .. w*4+3 (32 cols each)
#pragma unroll
        for (int k2 = 0; k2 < 4; k2++) {
            int rr = w * 4 + k2;
            float v = Sc[rr * SSTR + lane];
            float mx = v;
#pragma unroll
            for (int off = 16; off > 0; off >>= 1)
                mx = fmaxf(mx, __shfl_xor_sync(0xffffffffu, mx, off));
            float mprev = rm[rr];
            float mnew = fmaxf(mprev, mx);
            float p = __expf(v - mnew);
            float ls = p;
#pragma unroll
            for (int off = 16; off > 0; off >>= 1)
                ls += __shfl_xor_sync(0xffffffffu, ls, off);
            float pe = __shfl_sync(0xffffffffu, p, (lane & 15) * 2);
            float po = __shfl_sync(0xffffffffu, p, (lane & 15) * 2 + 1);
            if (lane < 16) {
                uint32_t hh, ll;
                split2(pe, po, hh, ll);
                Ph[rr * PSTR + lane] = hh;
                Pl[rr * PSTR + lane] = ll;
            }
            if (lane == 0) {
                float f = __expf(mprev - mnew);
                rl[rr] = rl[rr] * f + ls;
                rm[rr] = mnew;
                rs[rr] = f;
            }
        }
        __syncthreads();

        // rescale + PV: warp computes 16 q-rows x 32 d-cols
        float f0 = rs[qm + g], f1 = rs[qm + g + 8];
#pragma unroll
        for (int nt = 0; nt < 4; nt++) {
            o[nt][0] *= f0; o[nt][1] *= f0;
            o[nt][2] *= f1; o[nt][3] *= f1;
        }
#pragma unroll
        for (int kstep = 0; kstep < 2; kstep++) {
            int base = kstep * 8;
            uint32_t ah0 = Ph[(qm + g) * PSTR + base + tig];
            uint32_t ah1 = Ph[(qm + g + 8) * PSTR + base + tig];
            uint32_t ah2 = Ph[(qm + g) * PSTR + base + tig + 4];
            uint32_t ah3 = Ph[(qm + g + 8) * PSTR + base + tig + 4];
            uint32_t al0 = Pl[(qm + g) * PSTR + base + tig];
            uint32_t al1 = Pl[(qm + g + 8) * PSTR + base + tig];
            uint32_t al2 = Pl[(qm + g) * PSTR + base + tig + 4];
            uint32_t al3 = Pl[(qm + g + 8) * PSTR + base + tig + 4];
#pragma unroll
            for (int nt = 0; nt < 4; nt++) {
                int drow = dB + nt * 8 + g;
                uint32_t bh0 = Vh[drow * VSTR + base + tig];
                uint32_t bh1 = Vh[drow * VSTR + base + tig + 4];
                uint32_t bl0 = Vl[drow * VSTR + base + tig];
                uint32_t bl1 = Vl[drow * VSTR + base + tig + 4];
                mma_bf16(o[nt], ah0, ah1, ah2, ah3, bh0, bh1);
                mma_bf16(o[nt], ah0, ah1, ah2, ah3, bl0, bl1);
                mma_bf16(o[nt], al0, al1, al2, al3, bh0, bh1);
            }
        }
    }

    int pbase = (bk * NSPLIT + sp) * 32;
    if (t < 32) { g_pm[pbase + t] = rm[t]; g_pl[pbase + t] = rl[t]; }
#pragma unroll
    for (int nt = 0; nt < 4; nt++) {
        int col = dB + nt * 8 + tig * 2;
        int r0 = qm + g, r1 = qm + g + 8;
        g_po[(size_t)(pbase + r0) * DH + col]     = o[nt][0];
        g_po[(size_t)(pbase + r0) * DH + col + 1] = o[nt][1];
        g_po[(size_t)(pbase + r1) * DH + col]     = o[nt][2];
        g_po[(size_t)(pbase + r1) * DH + col + 1] = o[nt][3];
    }
}

// ---------------------------------------------------------------------------
// Merge split partials (log-sum-exp) + relayout to [(b,qq)][h*128+d]
// ---------------------------------------------------------------------------
__global__ void merge_kernel() {
    int i = blockIdx.x * 256 + threadIdx.x;   // 0 .. 262143
    int d = i & 127;
    int rg = i >> 7;
    int bk = rg >> 5, r = rg & 31;
    float mv[NSPLIT];
    float mmax = -INFINITY;
#pragma unroll
    for (int sp = 0; sp < NSPLIT; sp++) {
        mv[sp] = g_pm[(bk * NSPLIT + sp) * 32 + r];
        mmax = fmaxf(mmax, mv[sp]);
    }
    float num = 0.f, den = 0.f;
#pragma unroll
    for (int sp = 0; sp < NSPLIT; sp++) {
        float wgt = __expf(mv[sp] - mmax);
        num += wgt * g_po[(size_t)((bk * NSPLIT + sp) * 32 + r) * DH + d];
        den += wgt * g_pl[(bk * NSPLIT + sp) * 32 + r];
    }
    float val = num / den;
    int b = bk >> 3, kvh = bk & 7, gg = r >> 3, qq = r & 7;
    int h = kvh * NG + gg;
    g_attn[(b * NQ + qq) * HID + h * DH + d] = val;
}

// ---------------------------------------------------------------------------
// kernel_launch
// ---------------------------------------------------------------------------
extern "C" void kernel_launch(void* const* d_in, const int* in_sizes, int n_in,
                              void* d_out, int out_size) {
    (void)in_sizes; (void)n_in; (void)out_size;
    const float* hidden = (const float*)d_in[0];
    const int* pos = (const int*)d_in[1];
    const float* kc = (const float*)d_in[2];
    const float* vc = (const float*)d_in[3];
    const float* qw = (const float*)d_in[5];
    const float* ow = (const float*)d_in[6];
    float* out = (float*)d_out;

    static int attr_done = 0;
    if (!attr_done) {
        cudaFuncSetAttribute(attn_mma_kernel,
                             cudaFuncAttributeMaxDynamicSharedMemorySize,
                             SMEM_WORDS * 4);
        attr_done = 1;
    }

    rope_setup_kernel<<<1, 256>>>(pos);
    gemm_mma_kernel<<<dim3(HID / 64, KSPLIT), 256>>>(hidden, qw, 0);
    rope_reduce_kernel<<<512, 256>>>();
    attn_mma_kernel<<<64 * NSPLIT, 256, SMEM_WORDS * 4>>>(kc, vc);
    merge_kernel<<<1024, 256>>>();
    gemm_mma_kernel<<<dim3(HID / 64, KSPLIT), 256>>>(nullptr, ow, 1);
    reduce_out_kernel<<<1024, 256>>>(out);
}